// round 1
// baseline (speedup 1.0000x reference)
#include <cuda_runtime.h>
#include <cuda_bf16.h>
#include <cstddef>

// ----------------------------------------------------------------------------
// Problem constants (fixed shapes)
// ----------------------------------------------------------------------------
#define FC 32768        // coarse faces
#define FFINE 131072    // fine faces
#define CIN 128         // conv input channels
#define COUT0 128       // conv0 outputs
#define COUT1 96        // conv1 outputs
#define NCOL 3

// ----------------------------------------------------------------------------
// Device scratch (allocation-free rule: __device__ globals)
// ----------------------------------------------------------------------------
__device__ int   g_is64;
__device__ int   g_fn0[FC * 9];
__device__ int   g_fn1[FFINE * 9];
__device__ int   g_pm[FFINE];
__device__ float g_s[128 + 128 + 96];                 // s0, s1, s2
__device__ float g_W0[3 * CIN * COUT0];               // [c|s|r][i][o] transposed, modulated+demod
__device__ float g_W1[3 * CIN * COUT1];
__device__ float g_wrgbs[NCOL * COUT1];               // w_rgb * s2
__device__ float g_hc[(size_t)FC * CIN];              // conv0 raw output (pre-upsample)
__device__ float g_h1[(size_t)FFINE * CIN];           // upsampled + noise + act (conv1 input)
__device__ float g_imgpart[(size_t)FFINE * NCOL];     // smooth-upsampled img

// ----------------------------------------------------------------------------
// Helpers
// ----------------------------------------------------------------------------
__device__ __forceinline__ unsigned long long dup2(float g) {
    unsigned long long r;
    asm("mov.b64 %0, {%1, %1};" : "=l"(r) : "f"(g));
    return r;
}
__device__ __forceinline__ void ffma2(unsigned long long &acc, unsigned long long a,
                                      unsigned long long b) {
    asm("fma.rn.f32x2 %0, %1, %2, %0;" : "+l"(acc) : "l"(a), "l"(b));
}
__device__ __forceinline__ float2 upk(unsigned long long v) {
    float2 f;
    asm("mov.b64 {%0, %1}, %2;" : "=f"(f.x), "=f"(f.y) : "l"(v));
    return f;
}
__device__ __forceinline__ float actf(float v, float b) {
    v += b;
    v = (v > 0.0f) ? v : 0.2f * v;
    v *= 1.41421356237309515f;  // sqrt(2) act gain
    return fminf(256.0f, fmaxf(-256.0f, v));
}

// ----------------------------------------------------------------------------
// Index dtype detection + normalization to int32 scratch
// ----------------------------------------------------------------------------
__global__ void detect_kernel(const void *fn1raw) {
    if (threadIdx.x == 0 && blockIdx.x == 0) {
        const unsigned *u = (const unsigned *)fn1raw;
        int all0 = 1;
        for (int t = 0; t < 64; t++)
            if (u[2 * t + 1] != 0u) { all0 = 0; break; }
        g_is64 = all0;  // int64 values are small non-negative -> high words all zero
    }
}

template <int A>
__global__ void convert_kernel(const void *src) {
    constexpr int n = (A == 0) ? FC * 9 : ((A == 1) ? FFINE * 9 : FFINE);
    int *dst = (A == 0) ? g_fn0 : ((A == 1) ? g_fn1 : g_pm);
    int i = blockIdx.x * blockDim.x + threadIdx.x;
    if (i < n) {
        if (g_is64) dst[i] = (int)((const long long *)src)[i];
        else        dst[i] = ((const int *)src)[i];
    }
}

// ----------------------------------------------------------------------------
// Prep: styles (affine), demodulated+modulated weight matrices (transposed [i][o])
// ----------------------------------------------------------------------------
__global__ void prep_kernel(const float *__restrict__ ws,
                            const float *__restrict__ a0w, const float *__restrict__ a0b,
                            const float *__restrict__ a1w, const float *__restrict__ a1b,
                            const float *__restrict__ a2w, const float *__restrict__ a2b,
                            const float *__restrict__ wc0, const float *__restrict__ ws0,
                            const float *__restrict__ wr0,
                            const float *__restrict__ wc1, const float *__restrict__ ws1,
                            const float *__restrict__ wr1,
                            const float *__restrict__ wrgb) {
    const int t = threadIdx.x;
    const float inv512 = 0.044194173824159216f;  // 1/sqrt(512)
    const float inv96  = 0.10206207261596575f;   // 1/sqrt(96)
    if (t < 128) {
        const float *w = a0w + t * 512;
        float s = 0.f;
        for (int d = 0; d < 512; d++) s += ws[d] * w[d];
        g_s[t] = s * inv512 + a0b[t];
    } else if (t < 256) {
        int j = t - 128;
        const float *w = a1w + j * 512;
        const float *v = ws + 512;
        float s = 0.f;
        for (int d = 0; d < 512; d++) s += v[d] * w[d];
        g_s[128 + j] = s * inv512 + a1b[j];
    } else if (t < 352) {
        int j = t - 256;
        const float *w = a2w + j * 512;
        const float *v = ws + 1024;
        float s = 0.f;
        for (int d = 0; d < 512; d++) s += v[d] * w[d];
        g_s[256 + j] = (s * inv512 + a2b[j]) * inv96;  // torgb weight gain folded in
    }
    __syncthreads();
    if (t < 128) {
        // conv0 demod + modulated transposed weights, o = t
        float ss = 0.f;
        for (int i = 0; i < 128; i++) {
            float si = g_s[i];
            float a = wc0[t * 128 + i], b = ws0[t * 128 + i], c = wr0[t * 128 + i];
            ss += si * si * (a * a + 4.f * b * b + 4.f * c * c);
        }
        float d = 1.0f / sqrtf(ss + 1e-8f);
        for (int i = 0; i < 128; i++) {
            float si = g_s[i] * d;
            g_W0[i * COUT0 + t]                   = wc0[t * 128 + i] * si;
            g_W0[CIN * COUT0 + i * COUT0 + t]     = ws0[t * 128 + i] * si;
            g_W0[2 * CIN * COUT0 + i * COUT0 + t] = wr0[t * 128 + i] * si;
        }
    } else if (t < 224) {
        int o = t - 128;  // conv1, o < 96
        float ss = 0.f;
        for (int i = 0; i < 128; i++) {
            float si = g_s[128 + i];
            float a = wc1[o * 128 + i], b = ws1[o * 128 + i], c = wr1[o * 128 + i];
            ss += si * si * (a * a + 4.f * b * b + 4.f * c * c);
        }
        float d = 1.0f / sqrtf(ss + 1e-8f);
        for (int i = 0; i < 128; i++) {
            float si = g_s[128 + i] * d;
            g_W1[i * COUT1 + o]                   = wc1[o * 128 + i] * si;
            g_W1[CIN * COUT1 + i * COUT1 + o]     = ws1[o * 128 + i] * si;
            g_W1[2 * CIN * COUT1 + i * COUT1 + o] = wr1[o * 128 + i] * si;
        }
    } else if (t < 227) {
        int o = t - 224;
        for (int i = 0; i < 96; i++) g_wrgbs[o * 96 + i] = wrgb[o * 96 + i] * g_s[256 + i];
    }
}

// ----------------------------------------------------------------------------
// Modulated face conv + max over 9 positions.
// WHICH=0: coarse conv0 (inputs = concat(x, shape_feat), out -> g_hc, no epilogue)
// WHICH=1: fine conv1 (input = g_h1, out -> d_out h-region, noise+act epilogue)
//
// Block = 256 threads: 16 o-threads (each handles OUT/32 float2 output pairs at
// o = o_t*2 + p*32) x 16 f-threads (each 2 faces). Tile = 32 faces.
// Weights live in SMEM transposed [i][o]; per-k neighbor rows staged in SMEM.
// Inner loop is fma.rn.f32x2-bound (~128 scalar FMA/cyc/SM).
// ----------------------------------------------------------------------------
template <int WHICH>
__global__ void __launch_bounds__(256, 1)
conv_kernel(const float *__restrict__ xA, const float *__restrict__ xB,
            const float *__restrict__ nc, const float *__restrict__ nsp,
            const float *__restrict__ bias, float *__restrict__ out) {
    constexpr int IN = CIN;
    constexpr int OUT = (WHICH == 0) ? COUT0 : COUT1;
    constexpr int OP = OUT / 32;
    constexpr int FPT = 32;
    constexpr int INP = 132;  // padded SMEM row stride (bank-conflict avoidance)
    constexpr int NF = (WHICH == 0) ? FC : FFINE;

    extern __shared__ float sm[];
    float *Wsm = sm;                           // 3*IN*OUT
    float *Gk = sm + 3 * IN * OUT;             // FPT*INP
    int *rows = (int *)(Gk + FPT * INP);       // FPT*9

    const float *Wglob = (WHICH == 0) ? g_W0 : g_W1;
    const int *fn = (WHICH == 0) ? g_fn0 : g_fn1;

    // load weights once per block (float4)
    for (int t = threadIdx.x; t < 3 * IN * OUT / 4; t += 256)
        ((float4 *)Wsm)[t] = ((const float4 *)Wglob)[t];

    const int o_t = threadIdx.x & 15;
    const int f_t = threadIdx.x >> 4;
    const int nTiles = NF / FPT;

    for (int tile = blockIdx.x; tile < nTiles; tile += gridDim.x) {
        __syncthreads();
        const int fbase = tile * FPT;
        for (int t = threadIdx.x; t < FPT * 9; t += 256) {
            int v = fn[fbase * 9 + t];
            rows[t] = (v < NF) ? v : -1;
        }

        float2 mx[2][OP];
#pragma unroll
        for (int f2 = 0; f2 < 2; f2++)
#pragma unroll
            for (int p = 0; p < OP; p++) {
                mx[f2][p].x = -3.4e38f;
                mx[f2][p].y = -3.4e38f;
            }

        for (int k = 0; k < 9; k++) {
            __syncthreads();
            // stage gathered neighbor rows for this k
#pragma unroll
            for (int q = threadIdx.x; q < FPT * 32; q += 256) {
                int f = q >> 5, i4 = q & 31;
                int r = rows[f * 9 + k];
                float4 v = make_float4(0.f, 0.f, 0.f, 0.f);
                if (r >= 0) {
                    if (WHICH == 0) {
                        if (i4 < 24)
                            v = __ldg((const float4 *)(xA + (size_t)r * 96) + i4);
                        else
                            v = __ldg((const float4 *)(xB + (size_t)r * 32) + (i4 - 24));
                    } else {
                        v = __ldg((const float4 *)(g_h1 + (size_t)r * 128) + i4);
                    }
                }
                *(float4 *)&Gk[f * INP + i4 * 4] = v;
            }
            __syncthreads();

            const float *Wk = Wsm + ((k == 0) ? 0 : ((k < 5) ? 1 : 2)) * IN * OUT;
            unsigned long long acc[2][OP];
#pragma unroll
            for (int f2 = 0; f2 < 2; f2++)
#pragma unroll
                for (int p = 0; p < OP; p++) acc[f2][p] = 0ull;

            const float *g0 = &Gk[(f_t * 2) * INP];
            const float *g1 = g0 + INP;

            for (int i = 0; i < IN; i += 4) {
                float ga[4], gb[4];
                *(float4 *)ga = *(const float4 *)(g0 + i);
                *(float4 *)gb = *(const float4 *)(g1 + i);
#pragma unroll
                for (int u = 0; u < 4; u++) {
                    const float *wrow = Wk + (i + u) * OUT + o_t * 2;
                    unsigned long long w[OP];
#pragma unroll
                    for (int p = 0; p < OP; p++)
                        w[p] = *(const unsigned long long *)(wrow + p * 32);
                    unsigned long long ga2 = dup2(ga[u]);
                    unsigned long long gb2 = dup2(gb[u]);
#pragma unroll
                    for (int p = 0; p < OP; p++) {
                        ffma2(acc[0][p], ga2, w[p]);
                        ffma2(acc[1][p], gb2, w[p]);
                    }
                }
            }
#pragma unroll
            for (int f2 = 0; f2 < 2; f2++)
#pragma unroll
                for (int p = 0; p < OP; p++) {
                    float2 a = upk(acc[f2][p]);
                    mx[f2][p].x = fmaxf(mx[f2][p].x, a.x);
                    mx[f2][p].y = fmaxf(mx[f2][p].y, a.y);
                }
        }

        // epilogue + store
#pragma unroll
        for (int f2 = 0; f2 < 2; f2++) {
            int face = fbase + f_t * 2 + f2;
            float noise = 0.f;
            if (WHICH == 1) noise = nc[face] * nsp[0];
#pragma unroll
            for (int p = 0; p < OP; p++) {
                int o = o_t * 2 + p * 32;
                float2 v = mx[f2][p];
                if (WHICH == 1) {
                    v.x = actf(v.x + noise, bias[o]);
                    v.y = actf(v.y + noise, bias[o + 1]);
                    *(float2 *)&out[(size_t)face * COUT1 + o] = v;
                } else {
                    *(float2 *)&g_hc[(size_t)face * COUT0 + o] = v;
                }
            }
        }
    }
}

// ----------------------------------------------------------------------------
// Smooth upsample (coarse->fine, 9-neighborhood mean) + noise0 + act -> g_h1.
// Also produces the upsampled img partial.
// One warp per fine face; float4 per lane covers 128 channels.
// ----------------------------------------------------------------------------
__global__ void __launch_bounds__(256) upsample_kernel(const float *__restrict__ img,
                                                       const float *__restrict__ nc0,
                                                       const float *__restrict__ ns0,
                                                       const float *__restrict__ bias0) {
    const int warp = threadIdx.x >> 5, lane = threadIdx.x & 31;
    const int face = blockIdx.x * 8 + warp;
    int rows[9];
#pragma unroll
    for (int k = 0; k < 9; k++) {
        int v = g_fn1[face * 9 + k];
        rows[k] = (v < FFINE) ? g_pm[v] : -1;
    }
    float4 a = make_float4(0.f, 0.f, 0.f, 0.f);
#pragma unroll
    for (int k = 0; k < 9; k++) {
        if (rows[k] >= 0) {
            float4 v = __ldg((const float4 *)(g_hc + (size_t)rows[k] * 128) + lane);
            a.x += v.x; a.y += v.y; a.z += v.z; a.w += v.w;
        }
    }
    const float inv9 = 1.0f / 9.0f;
    float noise = nc0[face] * ns0[0];
    int c = lane * 4;
    float4 b = *(const float4 *)&bias0[c];
    float4 r;
    r.x = actf(a.x * inv9 + noise, b.x);
    r.y = actf(a.y * inv9 + noise, b.y);
    r.z = actf(a.z * inv9 + noise, b.z);
    r.w = actf(a.w * inv9 + noise, b.w);
    *(float4 *)&g_h1[(size_t)face * 128 + c] = r;

    if (lane < 3) {
        float s = 0.f;
#pragma unroll
        for (int k = 0; k < 9; k++)
            if (rows[k] >= 0) s += img[rows[k] * 3 + lane];
        g_imgpart[(size_t)face * 3 + lane] = s * inv9;
    }
}

// ----------------------------------------------------------------------------
// toRGB: y = clip(h[fn1[:,0]] . (w_rgb*s2) + bias_rgb), img_out = imgpart + y
// One warp per fine face.
// ----------------------------------------------------------------------------
__global__ void __launch_bounds__(256) torgb_kernel(const float *__restrict__ brgb,
                                                    float *__restrict__ dout) {
    const float *hout = dout;  // h region of output
    float *imgout = dout + (size_t)FFINE * COUT1;
    const int warp = threadIdx.x >> 5, lane = threadIdx.x & 31;
    const int face = blockIdx.x * 8 + warp;
    int idx = g_fn1[face * 9];
    float x0 = 0.f, x1 = 0.f, x2 = 0.f;
    if (idx < FFINE) {
        const float *hr = hout + (size_t)idx * COUT1;
        x0 = hr[lane]; x1 = hr[lane + 32]; x2 = hr[lane + 64];
    }
#pragma unroll
    for (int o = 0; o < 3; o++) {
        float p = x0 * g_wrgbs[o * 96 + lane] + x1 * g_wrgbs[o * 96 + lane + 32] +
                  x2 * g_wrgbs[o * 96 + lane + 64];
#pragma unroll
        for (int s = 16; s > 0; s >>= 1) p += __shfl_xor_sync(0xffffffffu, p, s);
        if (lane == 0) {
            float y = p + brgb[o];
            y = fminf(256.0f, fmaxf(-256.0f, y));
            imgout[(size_t)face * 3 + o] = g_imgpart[(size_t)face * 3 + o] + y;
        }
    }
}

// ----------------------------------------------------------------------------
// Host launcher
// ----------------------------------------------------------------------------
extern "C" void kernel_launch(void *const *d_in, const int *in_sizes, int n_in,
                              void *d_out, int out_size) {
    // pad0/pad1 scalar inputs may or may not be materialized; weights are the
    // last 20 inputs either way.
    int base = n_in - 20;

    const float *x   = (const float *)d_in[0];
    const float *sf  = (const float *)d_in[1];
    const float *img = (const float *)d_in[2];
    const float *ws  = (const float *)d_in[3];
    const void  *fn0 = d_in[4];
    const void  *fn1 = d_in[5];
    const void  *pm  = d_in[6];

    const float *a0w  = (const float *)d_in[base + 0];
    const float *a0b  = (const float *)d_in[base + 1];
    const float *wc0  = (const float *)d_in[base + 2];
    const float *ws0  = (const float *)d_in[base + 3];
    const float *wr0  = (const float *)d_in[base + 4];
    const float *ns0  = (const float *)d_in[base + 5];
    const float *b0   = (const float *)d_in[base + 6];
    const float *nc0  = (const float *)d_in[base + 7];
    const float *a1w  = (const float *)d_in[base + 8];
    const float *a1b  = (const float *)d_in[base + 9];
    const float *wc1  = (const float *)d_in[base + 10];
    const float *ws1  = (const float *)d_in[base + 11];
    const float *wr1  = (const float *)d_in[base + 12];
    const float *ns1  = (const float *)d_in[base + 13];
    const float *b1   = (const float *)d_in[base + 14];
    const float *nc1  = (const float *)d_in[base + 15];
    const float *a2w  = (const float *)d_in[base + 16];
    const float *a2b  = (const float *)d_in[base + 17];
    const float *wrgb = (const float *)d_in[base + 18];
    const float *brgb = (const float *)d_in[base + 19];

    const int SMEM0 = 3 * CIN * COUT0 * 4 + 32 * 132 * 4 + 32 * 9 * 4;  // 214656
    const int SMEM1 = 3 * CIN * COUT1 * 4 + 32 * 132 * 4 + 32 * 9 * 4;  // 165504
    cudaFuncSetAttribute(conv_kernel<0>, cudaFuncAttributeMaxDynamicSharedMemorySize, SMEM0);
    cudaFuncSetAttribute(conv_kernel<1>, cudaFuncAttributeMaxDynamicSharedMemorySize, SMEM1);

    int sms = 148;
    cudaDeviceGetAttribute(&sms, cudaDevAttrMultiProcessorCount, 0);

    detect_kernel<<<1, 32>>>(fn1);
    convert_kernel<0><<<(FC * 9 + 255) / 256, 256>>>(fn0);
    convert_kernel<1><<<(FFINE * 9 + 255) / 256, 256>>>(fn1);
    convert_kernel<2><<<(FFINE + 255) / 256, 256>>>(pm);
    prep_kernel<<<1, 512>>>(ws, a0w, a0b, a1w, a1b, a2w, a2b,
                            wc0, ws0, wr0, wc1, ws1, wr1, wrgb);

    float *out = (float *)d_out;
    conv_kernel<0><<<sms, 256, SMEM0>>>(x, sf, nc0, ns0, b0, out);
    upsample_kernel<<<FFINE / 8, 256>>>(img, nc0, ns0, b0);
    conv_kernel<1><<<sms, 256, SMEM1>>>(x, sf, nc1, ns1, b1, out);

    if (out_size >= (long long)FFINE * (COUT1 + NCOL))
        torgb_kernel<<<FFINE / 8, 256>>>(brgb, out);
}